// round 12
// baseline (speedup 1.0000x reference)
#include <cuda_runtime.h>
#include <cuda_fp16.h>
#include <cstdint>

// ---------------------------------------------------------------------------
// TeamMovementModel R12: R9 structure (fused gate-ownership HMMA LSTM,
// 1 barrier/step) with f16-accumulator MMA chains (even/odd kt, depth 4,
// zero-started; bias + x-proj kept exact fp32 and merged before activation).
// Tests whether B300 fallback HMMA f16-acc runs at 2x the f32-acc rate.
// fc_kernel rewritten as direct-global (one output/thread).
//   92 CTAs x 16 seqs, 512 threads, K=128 fp16, fp32 c-state.
// ---------------------------------------------------------------------------

#define Hh        128
#define GATES     512
#define Tt        128
#define SEQS      16
#define NCTAS     92
#define PCTAS     88
#define NPLAYER   1408
#define NBALL     64
#define THREADS   512
#define NKT       8             // K tiles of 16 (K=128)
#define BS        136           // h tile row stride in halves (conflict-free)

__device__ float g_hid[(NPLAYER + NBALL) * Hh];

__device__ __forceinline__ float tanhap(float x) {
    float y; asm("tanh.approx.f32 %0, %1;" : "=f"(y) : "f"(x)); return y;
}
__device__ __forceinline__ float sigap(float x) {
    return fmaf(0.5f, tanhap(0.5f * x), 0.5f);
}
__device__ __forceinline__ uint32_t h2pack(float a, float b) {
    __half2 h = __halves2half2(__float2half(a), __float2half(b));
    return *reinterpret_cast<uint32_t*>(&h);
}

// m16n8k16 row.col f16 accumulate (2 regs = 4 halves), accumulate in place.
__device__ __forceinline__ void mma16816h(uint32_t* d, const uint32_t* a,
                                          uint32_t b0, uint32_t b1) {
    asm volatile(
        "mma.sync.aligned.m16n8k16.row.col.f16.f16.f16.f16 "
        "{%0,%1}, {%2,%3,%4,%5}, {%6,%7}, {%0,%1};"
        : "+r"(d[0]), "+r"(d[1])
        : "r"(a[0]), "r"(a[1]), "r"(a[2]), "r"(a[3]), "r"(b0), "r"(b1));
}

__device__ __forceinline__ float2 h2f2(uint32_t v) {
    return __half22float2(*reinterpret_cast<__half2*>(&v));
}

__global__ __launch_bounds__(THREADS, 1)
void lstm_hmma_kernel(const float* __restrict__ xp, const float* __restrict__ xb,
                      const float* __restrict__ p_wih, const float* __restrict__ p_whh,
                      const float* __restrict__ p_bih, const float* __restrict__ p_bhh,
                      const float* __restrict__ b_wih, const float* __restrict__ b_whh,
                      const float* __restrict__ b_bih, const float* __restrict__ b_bhh)
{
    __shared__ float2 xs[Tt * SEQS];              // [t][s]     16 KB
    __shared__ __half Bsm[2 * SEQS * BS];         // ping-pong h tiles, 8.5 KB

    const int tid = threadIdx.x;
    const int w   = tid >> 5;          // 0..15 -> units [8w, 8w+8)
    const int ln  = tid & 31;
    const int cta = blockIdx.x;
    const bool is_ball = (cta >= PCTAS);

    const float* wih_ = is_ball ? b_wih : p_wih;
    const float* whh_ = is_ball ? b_whh : p_whh;
    const float* bih_ = is_ball ? b_bih : p_bih;
    const float* bhh_ = is_ball ? b_bhh : p_bhh;
    const float* xsrc = is_ball ? xb : xp;
    const int s0    = is_ball ? (cta - PCTAS) * SEQS : cta * SEQS;
    const int gbase = is_ball ? NPLAYER + s0 : s0;

    // ---- zero both h buffers, stage x ----
    for (int i = tid; i < 2 * SEQS * BS / 2; i += THREADS)
        reinterpret_cast<uint32_t*>(Bsm)[i] = 0;
    for (int i = tid; i < Tt * SEQS; i += THREADS) {
        int s = i >> 7, t = i & 127;
        xs[t * SEQS + s] = *reinterpret_cast<const float2*>(
            xsrc + (size_t)(s0 + s) * 256 + t * 2);
    }

    const int r0 = ln >> 2;            // 0..7
    const int c0 = (ln & 3) * 2;       // 0,2,4,6
    const int u  = w * 8 + r0;         // hidden unit owned by this thread

    // ---- A fragments: mt0 rows = {i(u), f(u)}, mt1 rows = {g(u), o(u)} ----
    uint32_t Af[2][NKT][4];
    #pragma unroll
    for (int mt = 0; mt < 2; mt++) {
        const float* wrA = whh_ + (size_t)((mt * 2 + 0) * Hh + u) * Hh;  // i or g
        const float* wrB = whh_ + (size_t)((mt * 2 + 1) * Hh + u) * Hh;  // f or o
        #pragma unroll
        for (int kt = 0; kt < NKT; kt++) {
            const int k = kt * 16 + c0;
            float2 aA0 = *reinterpret_cast<const float2*>(wrA + k);
            float2 aB0 = *reinterpret_cast<const float2*>(wrB + k);
            float2 aA1 = *reinterpret_cast<const float2*>(wrA + k + 8);
            float2 aB1 = *reinterpret_cast<const float2*>(wrB + k + 8);
            Af[mt][kt][0] = h2pack(aA0.x, aA0.y);
            Af[mt][kt][1] = h2pack(aB0.x, aB0.y);
            Af[mt][kt][2] = h2pack(aA1.x, aA1.y);
            Af[mt][kt][3] = h2pack(aB1.x, aB1.y);
        }
    }

    // ---- per-gate x-weights and bias for unit u ----
    float wx0[4], wx1[4], bsr[4];
    #pragma unroll
    for (int q = 0; q < 4; q++) {
        const int g = q * Hh + u;
        wx0[q] = wih_[g * 2 + 0];
        wx1[q] = wih_[g * 2 + 1];
        bsr[q] = bih_[g] + bhh_[g];
    }

    float c[4] = {0.f, 0.f, 0.f, 0.f};

    __syncthreads();

    for (int t = 0; t < Tt; t++) {
        const __half* Bcur = Bsm + (t & 1) * (SEQS * BS);
        __half*       Bnxt = Bsm + ((t + 1) & 1) * (SEQS * BS);

        // ---- exact fp32 bias + x-projection (merged after the MMAs) ----
        // X[mt][nt][e]: e0,e1 = gate A seqs (s, s+1); e2,e3 = gate B.
        float X[2][2][4];
        #pragma unroll
        for (int nt = 0; nt < 2; nt++) {
            #pragma unroll
            for (int e1 = 0; e1 < 2; e1++) {
                const int s = nt * 8 + c0 + e1;
                const float2 x = xs[t * SEQS + s];
                X[0][nt][e1]     = fmaf(wx1[0], x.y, fmaf(wx0[0], x.x, bsr[0]));
                X[0][nt][2 + e1] = fmaf(wx1[1], x.y, fmaf(wx0[1], x.x, bsr[1]));
                X[1][nt][e1]     = fmaf(wx1[2], x.y, fmaf(wx0[2], x.x, bsr[2]));
                X[1][nt][2 + e1] = fmaf(wx1[3], x.y, fmaf(wx0[3], x.x, bsr[3]));
            }
        }

        // ---- f16-acc MMA chains, zero-started: even kt -> Dh, odd kt -> Eh ----
        // reg0 = row r0 (gate A) cols (c, c+1); reg1 = row r0+8 (gate B).
        uint32_t Dh[2][2][2] = {}, Eh[2][2][2] = {};
        #pragma unroll
        for (int kt = 0; kt < NKT; kt++) {
            const int kh = kt * 16 + c0;
            const __half* bp0 = Bcur + r0 * BS + kh;
            const __half* bp1 = bp0 + 8 * BS;
            const uint32_t b00 = *reinterpret_cast<const uint32_t*>(bp0);
            const uint32_t b01 = *reinterpret_cast<const uint32_t*>(bp0 + 8);
            const uint32_t b10 = *reinterpret_cast<const uint32_t*>(bp1);
            const uint32_t b11 = *reinterpret_cast<const uint32_t*>(bp1 + 8);
            uint32_t (*T)[2][2] = (kt & 1) ? Eh : Dh;
            mma16816h(T[0][0], Af[0][kt], b00, b01);
            mma16816h(T[0][1], Af[0][kt], b10, b11);
            mma16816h(T[1][0], Af[1][kt], b00, b01);
            mma16816h(T[1][1], Af[1][kt], b10, b11);
        }

        // ---- merge (fp32) + in-register LSTM cell update ----
        #pragma unroll
        for (int j = 0; j < 4; j++) {
            const int nt = j >> 1, e1 = j & 1;
            const int m  = nt * 8 + c0 + e1;
            const float2 dA0 = h2f2(Dh[0][nt][0]), eA0 = h2f2(Eh[0][nt][0]);
            const float2 dB0 = h2f2(Dh[0][nt][1]), eB0 = h2f2(Eh[0][nt][1]);
            const float2 dA1 = h2f2(Dh[1][nt][0]), eA1 = h2f2(Eh[1][nt][0]);
            const float2 dB1 = h2f2(Dh[1][nt][1]), eB1 = h2f2(Eh[1][nt][1]);
            const float pi = X[0][nt][e1]     + (e1 ? dA0.y + eA0.y : dA0.x + eA0.x);
            const float pf = X[0][nt][2 + e1] + (e1 ? dB0.y + eB0.y : dB0.x + eB0.x);
            const float pg = X[1][nt][e1]     + (e1 ? dA1.y + eA1.y : dA1.x + eA1.x);
            const float po = X[1][nt][2 + e1] + (e1 ? dB1.y + eB1.y : dB1.x + eB1.x);
            const float gi = sigap(pi);
            const float gf = sigap(pf);
            const float gg = tanhap(pg);
            const float go = sigap(po);
            c[j] = gf * c[j] + gi * gg;
            const float h = go * tanhap(c[j]);
            Bnxt[m * BS + u] = __float2half(h);
            if (t == Tt - 1)
                g_hid[(size_t)(gbase + m) * Hh + u] = h;
        }
        __syncthreads();   // h(t+1) visible before anyone reads Bnxt
    }
}

// FC: direct-global, one output element per thread. 440 x 128 = 56320 = 1408*40.
__global__ __launch_bounds__(128)
void fc_kernel(const float* __restrict__ fc_w,
               const float* __restrict__ fc_b,
               float* __restrict__ out)
{
    const int o = blockIdx.x * 128 + threadIdx.x;   // 0..56319
    const int s = o / 40;
    const int j = o - s * 40;
    const int b = s / 22;

    const float4* wr = reinterpret_cast<const float4*>(fc_w + j * 256);
    const float4* hp = reinterpret_cast<const float4*>(g_hid + (size_t)s * Hh);
    const float4* hb = reinterpret_cast<const float4*>(g_hid + (size_t)(NPLAYER + b) * Hh);

    float acc = fc_b[j];
    #pragma unroll 8
    for (int k = 0; k < 32; k++) {
        const float4 wv = wr[k];
        const float4 hv = hp[k];
        acc = fmaf(wv.x, hv.x, acc);
        acc = fmaf(wv.y, hv.y, acc);
        acc = fmaf(wv.z, hv.z, acc);
        acc = fmaf(wv.w, hv.w, acc);
    }
    #pragma unroll 8
    for (int k = 0; k < 32; k++) {
        const float4 wv = wr[32 + k];
        const float4 hv = hb[k];
        acc = fmaf(wv.x, hv.x, acc);
        acc = fmaf(wv.y, hv.y, acc);
        acc = fmaf(wv.z, hv.z, acc);
        acc = fmaf(wv.w, hv.w, acc);
    }
    out[o] = acc;
}

extern "C" void kernel_launch(void* const* d_in, const int* in_sizes, int n_in,
                              void* d_out, int out_size)
{
    const float* xp    = (const float*)d_in[0];
    const float* xb    = (const float*)d_in[1];
    const float* p_wih = (const float*)d_in[2];
    const float* p_whh = (const float*)d_in[3];
    const float* p_bih = (const float*)d_in[4];
    const float* p_bhh = (const float*)d_in[5];
    const float* b_wih = (const float*)d_in[6];
    const float* b_whh = (const float*)d_in[7];
    const float* b_bih = (const float*)d_in[8];
    const float* b_bhh = (const float*)d_in[9];
    const float* fc_w  = (const float*)d_in[10];
    const float* fc_b  = (const float*)d_in[11];
    float* out = (float*)d_out;

    lstm_hmma_kernel<<<NCTAS, THREADS>>>(xp, xb,
                                         p_wih, p_whh, p_bih, p_bhh,
                                         b_wih, b_whh, b_bih, b_bhh);
    fc_kernel<<<440, 128>>>(fc_w, fc_b, out);
}

// round 13
// speedup vs baseline: 1.1830x; 1.1830x over previous
#include <cuda_runtime.h>
#include <cuda_fp16.h>
#include <cstdint>

// ---------------------------------------------------------------------------
// TeamMovementModel R13: R9 (fused gate-ownership HMMA LSTM, fp32 acc,
// 1 barrier/step) consolidated + x-prefetch into registers (shortens the
// post-barrier critical path) + unroll-2 ping-pong (compile-time buffers).
// R12's f16-acc and direct-global fc both reverted (measured regressions).
//   92 CTAs x 16 seqs, 512 threads, K=128 fp16, fp32 c-state.
// ---------------------------------------------------------------------------

#define Hh        128
#define GATES     512
#define Tt        128
#define SEQS      16
#define NCTAS     92
#define PCTAS     88
#define NPLAYER   1408
#define NBALL     64
#define THREADS   512
#define NKT       8             // K tiles of 16 (K=128)
#define BS        136           // h tile row stride in halves (conflict-free)

__device__ float g_hid[(NPLAYER + NBALL) * Hh];

__device__ __forceinline__ float tanhap(float x) {
    float y; asm("tanh.approx.f32 %0, %1;" : "=f"(y) : "f"(x)); return y;
}
__device__ __forceinline__ float sigap(float x) {
    return fmaf(0.5f, tanhap(0.5f * x), 0.5f);
}
__device__ __forceinline__ uint32_t h2pack(float a, float b) {
    __half2 h = __halves2half2(__float2half(a), __float2half(b));
    return *reinterpret_cast<uint32_t*>(&h);
}

// m16n8k16 row.col f32.f16.f16.f32, accumulate in place.
__device__ __forceinline__ void mma16816(float* d, const uint32_t* a,
                                         uint32_t b0, uint32_t b1) {
    asm volatile(
        "mma.sync.aligned.m16n8k16.row.col.f32.f16.f16.f32 "
        "{%0,%1,%2,%3}, {%4,%5,%6,%7}, {%8,%9}, {%0,%1,%2,%3};"
        : "+f"(d[0]), "+f"(d[1]), "+f"(d[2]), "+f"(d[3])
        : "r"(a[0]), "r"(a[1]), "r"(a[2]), "r"(a[3]), "r"(b0), "r"(b1));
}

struct StepState {
    uint32_t (*Af)[NKT][4];     // [2][NKT][4]
    const float* wx0; const float* wx1; const float* bsr;
    float* c;                   // [4]
    int r0, c0, u, gbase;
};

// One LSTM step: reads h from Bcur, writes h(t+1) to Bnxt. xf[4] = x(t) regs.
// Returns nothing; caller prefetches xf for t+1 and does the barrier.
__device__ __forceinline__ void lstm_step(
    const StepState& S, const __half* Bcur, __half* Bnxt,
    const float2* xf, bool last, float* g_out)
{
    // ---- D init: bias + exact fp32 x-projection from registers ----
    float D[2][2][4];
    #pragma unroll
    for (int nt = 0; nt < 2; nt++) {
        #pragma unroll
        for (int e1 = 0; e1 < 2; e1++) {
            const float2 x = xf[nt * 2 + e1];
            D[0][nt][e1]     = fmaf(S.wx1[0], x.y, fmaf(S.wx0[0], x.x, S.bsr[0]));
            D[0][nt][2 + e1] = fmaf(S.wx1[1], x.y, fmaf(S.wx0[1], x.x, S.bsr[1]));
            D[1][nt][e1]     = fmaf(S.wx1[2], x.y, fmaf(S.wx0[2], x.x, S.bsr[2]));
            D[1][nt][2 + e1] = fmaf(S.wx1[3], x.y, fmaf(S.wx0[3], x.x, S.bsr[3]));
        }
    }

    // ---- recurrent GEMM over h (K=128) ----
    #pragma unroll
    for (int kt = 0; kt < NKT; kt++) {
        const int kh = kt * 16 + S.c0;
        const __half* bp0 = Bcur + S.r0 * BS + kh;
        const __half* bp1 = bp0 + 8 * BS;
        const uint32_t b00 = *reinterpret_cast<const uint32_t*>(bp0);
        const uint32_t b01 = *reinterpret_cast<const uint32_t*>(bp0 + 8);
        const uint32_t b10 = *reinterpret_cast<const uint32_t*>(bp1);
        const uint32_t b11 = *reinterpret_cast<const uint32_t*>(bp1 + 8);
        mma16816(D[0][0], S.Af[0][kt], b00, b01);
        mma16816(D[0][1], S.Af[0][kt], b10, b11);
        mma16816(D[1][0], S.Af[1][kt], b00, b01);
        mma16816(D[1][1], S.Af[1][kt], b10, b11);
    }

    // ---- in-register LSTM cell update: all 4 gates local ----
    #pragma unroll
    for (int j = 0; j < 4; j++) {
        const int nt = j >> 1, e1 = j & 1;
        const int m  = nt * 8 + S.c0 + e1;
        const float gi = sigap(D[0][nt][e1]);
        const float gf = sigap(D[0][nt][2 + e1]);
        const float gg = tanhap(D[1][nt][e1]);
        const float go = sigap(D[1][nt][2 + e1]);
        S.c[j] = gf * S.c[j] + gi * gg;
        const float h = go * tanhap(S.c[j]);
        Bnxt[m * BS + S.u] = __float2half(h);
        if (last)
            g_out[(size_t)(S.gbase + m) * Hh + S.u] = h;
    }
}

__global__ __launch_bounds__(THREADS, 1)
void lstm_hmma_kernel(const float* __restrict__ xp, const float* __restrict__ xb,
                      const float* __restrict__ p_wih, const float* __restrict__ p_whh,
                      const float* __restrict__ p_bih, const float* __restrict__ p_bhh,
                      const float* __restrict__ b_wih, const float* __restrict__ b_whh,
                      const float* __restrict__ b_bih, const float* __restrict__ b_bhh)
{
    __shared__ float2 xs[Tt * SEQS];              // [t][s]     16 KB
    __shared__ __half B0[SEQS * BS];              // ping
    __shared__ __half B1[SEQS * BS];              // pong

    const int tid = threadIdx.x;
    const int w   = tid >> 5;          // 0..15 -> units [8w, 8w+8)
    const int ln  = tid & 31;
    const int cta = blockIdx.x;
    const bool is_ball = (cta >= PCTAS);

    const float* wih_ = is_ball ? b_wih : p_wih;
    const float* whh_ = is_ball ? b_whh : p_whh;
    const float* bih_ = is_ball ? b_bih : p_bih;
    const float* bhh_ = is_ball ? b_bhh : p_bhh;
    const float* xsrc = is_ball ? xb : xp;
    const int s0    = is_ball ? (cta - PCTAS) * SEQS : cta * SEQS;
    const int gbase = is_ball ? NPLAYER + s0 : s0;

    // ---- zero both h buffers, stage x ----
    for (int i = tid; i < SEQS * BS / 2; i += THREADS) {
        reinterpret_cast<uint32_t*>(B0)[i] = 0;
        reinterpret_cast<uint32_t*>(B1)[i] = 0;
    }
    for (int i = tid; i < Tt * SEQS; i += THREADS) {
        int s = i >> 7, t = i & 127;
        xs[t * SEQS + s] = *reinterpret_cast<const float2*>(
            xsrc + (size_t)(s0 + s) * 256 + t * 2);
    }

    const int r0 = ln >> 2;            // 0..7
    const int c0 = (ln & 3) * 2;       // 0,2,4,6
    const int u  = w * 8 + r0;         // hidden unit owned by this thread

    // ---- A fragments: mt0 rows = {i(u), f(u)}, mt1 rows = {g(u), o(u)} ----
    uint32_t Af[2][NKT][4];
    #pragma unroll
    for (int mt = 0; mt < 2; mt++) {
        const float* wrA = whh_ + (size_t)((mt * 2 + 0) * Hh + u) * Hh;  // i or g
        const float* wrB = whh_ + (size_t)((mt * 2 + 1) * Hh + u) * Hh;  // f or o
        #pragma unroll
        for (int kt = 0; kt < NKT; kt++) {
            const int k = kt * 16 + c0;
            float2 aA0 = *reinterpret_cast<const float2*>(wrA + k);
            float2 aB0 = *reinterpret_cast<const float2*>(wrB + k);
            float2 aA1 = *reinterpret_cast<const float2*>(wrA + k + 8);
            float2 aB1 = *reinterpret_cast<const float2*>(wrB + k + 8);
            Af[mt][kt][0] = h2pack(aA0.x, aA0.y);
            Af[mt][kt][1] = h2pack(aB0.x, aB0.y);
            Af[mt][kt][2] = h2pack(aA1.x, aA1.y);
            Af[mt][kt][3] = h2pack(aB1.x, aB1.y);
        }
    }

    // ---- per-gate x-weights and bias for unit u ----
    float wx0[4], wx1[4], bsr[4];
    #pragma unroll
    for (int q = 0; q < 4; q++) {
        const int g = q * Hh + u;
        wx0[q] = wih_[g * 2 + 0];
        wx1[q] = wih_[g * 2 + 1];
        bsr[q] = bih_[g] + bhh_[g];
    }

    float c[4] = {0.f, 0.f, 0.f, 0.f};

    StepState S;
    S.Af = Af; S.wx0 = wx0; S.wx1 = wx1; S.bsr = bsr; S.c = c;
    S.r0 = r0; S.c0 = c0; S.u = u; S.gbase = gbase;

    __syncthreads();

    // x prefetch registers for the current step (seqs c0, c0+1, 8+c0, 8+c0+1)
    float2 xf[4];
    xf[0] = xs[0 * SEQS + c0];     xf[1] = xs[0 * SEQS + c0 + 1];
    xf[2] = xs[0 * SEQS + 8 + c0]; xf[3] = xs[0 * SEQS + 8 + c0 + 1];

    #pragma unroll 1
    for (int t = 0; t < Tt; t += 2) {
        // step t: B0 -> B1
        lstm_step(S, B0, B1, xf, t == Tt - 1, g_hid);
        {
            const int tn = t + 1;
            xf[0] = xs[tn * SEQS + c0];     xf[1] = xs[tn * SEQS + c0 + 1];
            xf[2] = xs[tn * SEQS + 8 + c0]; xf[3] = xs[tn * SEQS + 8 + c0 + 1];
        }
        __syncthreads();
        // step t+1: B1 -> B0
        lstm_step(S, B1, B0, xf, t + 1 == Tt - 1, g_hid);
        if (t + 2 < Tt) {
            const int tn = t + 2;
            xf[0] = xs[tn * SEQS + c0];     xf[1] = xs[tn * SEQS + c0 + 1];
            xf[2] = xs[tn * SEQS + 8 + c0]; xf[3] = xs[tn * SEQS + 8 + c0 + 1];
        }
        __syncthreads();
    }
}

// FC: 128 blocks = (batch b, half of 22 players). fc_w + hidden states in smem.
#define FC_THREADS 448
__global__ __launch_bounds__(FC_THREADS)
void fc_kernel(const float* __restrict__ fc_w,
               const float* __restrict__ fc_b,
               float* __restrict__ out)
{
    __shared__ float fw[40 * 258];
    __shared__ float ph[11 * 128];
    __shared__ float ball[128];

    const int bx   = blockIdx.x;
    const int b    = bx >> 1;
    const int half = bx & 1;
    const int tid  = threadIdx.x;

    for (int idx = tid; idx < 40 * 256; idx += FC_THREADS) {
        int j = idx >> 8, k = idx & 255;
        fw[j * 258 + k] = fc_w[idx];
    }
    for (int idx = tid; idx < 11 * 128; idx += FC_THREADS) {
        int p = idx >> 7, k = idx & 127;
        ph[idx] = g_hid[(b * 22 + half * 11 + p) * Hh + k];
    }
    for (int idx = tid; idx < 128; idx += FC_THREADS)
        ball[idx] = g_hid[(NPLAYER + b) * Hh + idx];
    __syncthreads();

    if (tid < 440) {
        const int p = tid / 40;
        const int j = tid - p * 40;
        const float2* php  = (const float2*)(ph + p * 128);
        const float2* blp  = (const float2*)(ball);
        const float2* fwp0 = (const float2*)(fw + j * 258);
        const float2* fwp1 = (const float2*)(fw + j * 258 + 128);
        float acc = fc_b[j];
        #pragma unroll 8
        for (int k2 = 0; k2 < 64; k2++) {
            float2 hp = php[k2], hb = blp[k2];
            float2 w0 = fwp0[k2], w1 = fwp1[k2];
            acc += hp.x * w0.x + hp.y * w0.y + hb.x * w1.x + hb.y * w1.y;
        }
        out[(b * 22 + half * 11 + p) * 40 + j] = acc;
    }
}

extern "C" void kernel_launch(void* const* d_in, const int* in_sizes, int n_in,
                              void* d_out, int out_size)
{
    const float* xp    = (const float*)d_in[0];
    const float* xb    = (const float*)d_in[1];
    const float* p_wih = (const float*)d_in[2];
    const float* p_whh = (const float*)d_in[3];
    const float* p_bih = (const float*)d_in[4];
    const float* p_bhh = (const float*)d_in[5];
    const float* b_wih = (const float*)d_in[6];
    const float* b_whh = (const float*)d_in[7];
    const float* b_bih = (const float*)d_in[8];
    const float* b_bhh = (const float*)d_in[9];
    const float* fc_w  = (const float*)d_in[10];
    const float* fc_b  = (const float*)d_in[11];
    float* out = (float*)d_out;

    lstm_hmma_kernel<<<NCTAS, THREADS>>>(xp, xb,
                                         p_wih, p_whh, p_bih, p_bhh,
                                         b_wih, b_whh, b_bih, b_bhh);
    fc_kernel<<<128, FC_THREADS>>>(fc_w, fc_b, out);
}